// round 16
// baseline (speedup 1.0000x reference)
#include <cuda_runtime.h>
#include <cstdint>

#define B_   8
#define CIN  64
#define COUT 8
#define H1   128
#define W1   128
#define H2   256
#define W2   256
#define PLANE (H2*W2)   /* 65536 */
#define NUM_ 8
#define NSEG 16

// ---------------- scratch (device globals; no allocation allowed) ----------
__device__ float g_xf [(size_t)B_*COUT*PLANE];   // conv2+BN, thresholded
__device__ unsigned long long g_seg[B_*COUT*NSEG*8]; // per-segment top-8 keys

// ---------------- packed f32x2 helpers --------------------------------------
__device__ __forceinline__ unsigned long long pk2(float lo, float hi) {
    unsigned long long r;
    asm("mov.b64 %0, {%1, %2};" : "=l"(r) : "f"(lo), "f"(hi));
    return r;
}
__device__ __forceinline__ void upk2(unsigned long long v, float& lo, float& hi) {
    asm("mov.b64 {%0, %1}, %2;" : "=f"(lo), "=f"(hi) : "l"(v));
}
#define FMA2(d, a, b) asm("fma.rn.f32x2 %0, %1, %2, %0;" : "+l"(d) : "l"(a), "l"(b))

// dynamic smem layout for conv1 (full 64-co block)
#define C1_W_BYTES    (CIN * 9 * 32 * 8)            /* 147456 */
#define C1_IN_BYTES   (2 * 4 * 6 * 136 * 4)         /* 26112  */
#define C1_W2_BYTES   (8 * 64 * 8)                  /* 4096   */
#define C1_SS_BYTES   (2 * 64 * 4 + 2 * 8 * 4)      /* 576    */
#define C1_SMEM_TOTAL (C1_W_BYTES + C1_IN_BYTES + C1_W2_BYTES + C1_SS_BYTES)

// ============================================================================
// conv1: fused bilinear-2x-upsample + conv3x3(64->64) + bias + BN + ReLU
//        + COMPLETE conv1x1(64->8) + BN2 + threshold -> writes g_xf directly
// grid (2, 64, B): tile 128(w) x 4(h), all 64 co per block.
// block 512 = 32 xg * 4 yg * 4 cg; thread: 4 px * 16 co (8 pairs, FFMA2).
// 4 input channels per barrier round (16 rounds).
// ============================================================================
__global__ __launch_bounds__(512, 1) void k_conv1(
    const float* __restrict__ x,
    const float* __restrict__ w1, const float* __restrict__ b1,
    const float* __restrict__ gamma1, const float* __restrict__ beta1,
    const float* __restrict__ mean1, const float* __restrict__ var1,
    const float* __restrict__ w2,
    const float* __restrict__ gamma2, const float* __restrict__ beta2,
    const float* __restrict__ mean2, const float* __restrict__ var2)
{
    extern __shared__ __align__(16) unsigned char dsm[];
    unsigned long long (*s_w)[9][32] =
        (unsigned long long (*)[9][32])(dsm);                    // [ci][tap][pair]
    float (*s_in)[4][6][136] =
        (float (*)[4][6][136])(dsm + C1_W_BYTES);                // [buf][sub][r][c]
    unsigned long long (*s_w2)[64] =
        (unsigned long long (*)[64])(dsm + C1_W_BYTES + C1_IN_BYTES);
    float* s_scale = (float*)(dsm + C1_W_BYTES + C1_IN_BYTES + C1_W2_BYTES);
    float* s_shift  = s_scale + 64;
    float* s_scale2 = s_shift + 64;
    float* s_shift2 = s_scale2 + 8;

    const int tid = threadIdx.x;
    const int xg = tid & 31;
    const int yg = (tid >> 5) & 3;
    const int cg = tid >> 7;               // 0..3: which 16-co group of the 64
    const int b   = blockIdx.z;
    const int x0t = blockIdx.x * 128;
    const int y0t = blockIdx.y * 4;

    const float* xb = x + (size_t)b * CIN * (H1 * W1);

    for (int i = tid; i < CIN * 9 * 32; i += 512) {
        int cp = i & 31; int rest = i >> 5;
        int p = rest % 9; int ci = rest / 9;
        int coA = 2 * cp;
        float wa = w1[((size_t)coA       * CIN + ci) * 9 + p];
        float wb = w1[((size_t)(coA + 1) * CIN + ci) * 9 + p];
        s_w[ci][p][cp] = pk2(wa, wb);
    }
    if (tid < 64) {
        float a = gamma1[tid] * rsqrtf(var1[tid] + 1e-5f);
        s_scale[tid] = a;
        s_shift[tid] = fmaf(a, b1[tid] - mean1[tid], beta1[tid]);
    }
    if (tid >= 64 && tid < 72) {
        int co = tid - 64;
        float a = gamma2[co] * rsqrtf(var2[co] + 1e-5f);
        s_scale2[co] = a;
        s_shift2[co] = beta2[co] - a * mean2[co];
    }
    {   // s_w2: exactly 512 entries (8 co2 x 64 ci)
        int co2 = tid >> 6, j = tid & 63;
        float w = w2[co2 * 64 + j];
        s_w2[co2][j] = pk2(w, w);
    }

    const bool runA = tid < 198;
    const int ur  = tid / 33;
    const int c0r = (tid - ur * 33) * 4;
    const int gy  = y0t + ur - 1;
    const int gx0 = x0t + c0r - 1;
    const int sy  = (gy - 1) >> 1;
    const int ro0 = min(max(sy, 0), H1 - 1) * W1;
    const int ro1 = min(max(sy + 1, 0), H1 - 1) * W1;
    const float wyv = (gy & 1) ? 0.25f : 0.75f;
    const int S   = (gx0 - 1) >> 1;
    const int cS0 = min(max(S, 0), W1 - 1);
    const int cS1 = min(max(S + 1, 0), W1 - 1);
    const int cS2 = min(max(S + 2, 0), W1 - 1);
    const bool rowOK = (gy >= 0) && (gy < H2);
    bool mok[4];
#pragma unroll
    for (int j = 0; j < 4; j++) {
        int gx = gx0 + j;
        mok[j] = rowOK && (gx >= 0) && (gx < W2);
    }

#define BILIN(buf, sub, pa) do {                                              \
        float p0a = (pa)[0], p0b = (pa)[1], p0c = (pa)[2];                    \
        float p1a = (pa)[3], p1b = (pa)[4], p1c = (pa)[5];                    \
        float t0 = p0a + 0.25f * (p0b - p0a);                                 \
        float t1 = p0a + 0.75f * (p0b - p0a);                                 \
        float t2 = p0b + 0.25f * (p0c - p0b);                                 \
        float t3 = p0b + 0.75f * (p0c - p0b);                                 \
        float u0 = p1a + 0.25f * (p1b - p1a);                                 \
        float u1 = p1a + 0.75f * (p1b - p1a);                                 \
        float u2 = p1b + 0.25f * (p1c - p1b);                                 \
        float u3 = p1b + 0.75f * (p1c - p1b);                                 \
        float4 o;                                                             \
        o.x = mok[0] ? (t0 + wyv * (u0 - t0)) : 0.f;                          \
        o.y = mok[1] ? (t1 + wyv * (u1 - t1)) : 0.f;                          \
        o.z = mok[2] ? (t2 + wyv * (u2 - t2)) : 0.f;                          \
        o.w = mok[3] ? (t3 + wyv * (u3 - t3)) : 0.f;                          \
        *(float4*)&s_in[buf][sub][ur][c0r] = o;                               \
    } while (0)

#define LOAD6(ci, pa) do {                                                    \
        const float* xp_ = xb + ((size_t)(ci) << 14);                         \
        (pa)[0] = xp_[ro0 + cS0]; (pa)[1] = xp_[ro0 + cS1];                   \
        (pa)[2] = xp_[ro0 + cS2];                                             \
        (pa)[3] = xp_[ro1 + cS0]; (pa)[4] = xp_[ro1 + cS1];                   \
        (pa)[5] = xp_[ro1 + cS2];                                             \
    } while (0)

    if (runA) {
        float pf[4][6];
#pragma unroll
        for (int s = 0; s < 4; s++) LOAD6(s, pf[s]);
#pragma unroll
        for (int s = 0; s < 4; s++) BILIN(0, s, pf[s]);
    }
    __syncthreads();

    unsigned long long acc[4][8];
#pragma unroll
    for (int q = 0; q < 4; q++)
#pragma unroll
        for (int j = 0; j < 8; j++) acc[q][j] = 0ull;

    for (int cc = 0; cc < CIN; cc += 4) {
        const int cur = (cc >> 2) & 1;

        float pf[4][6];
        if (runA && cc + 4 < CIN) {
#pragma unroll
            for (int s = 0; s < 4; s++) LOAD6(cc + 4 + s, pf[s]);
        }

#pragma unroll
        for (int sub = 0; sub < 4; sub++) {
            const int ci = cc + sub;
#pragma unroll
            for (int kr = 0; kr < 3; kr++) {
                const float* row = &s_in[cur][sub][yg + kr][4 * xg];
                float4 F = *(const float4*)row;
                float2 G = *(const float2*)(row + 4);
                unsigned long long Q[6];
                Q[0] = pk2(F.x, F.x);
                Q[1] = pk2(F.y, F.y);
                Q[2] = pk2(F.z, F.z);
                Q[3] = pk2(F.w, F.w);
                Q[4] = pk2(G.x, G.x);
                Q[5] = pk2(G.y, G.y);
#pragma unroll
                for (int kc = 0; kc < 3; kc++) {
                    const ulonglong2* wrow =
                        (const ulonglong2*)&s_w[ci][kr * 3 + kc][cg * 8];
                    ulonglong2 wA = wrow[0];
                    ulonglong2 wB = wrow[1];
                    ulonglong2 wC = wrow[2];
                    ulonglong2 wD = wrow[3];
#pragma unroll
                    for (int q = 0; q < 4; q++) {
                        unsigned long long iv = Q[kc + q];
                        FMA2(acc[q][0], iv, wA.x);
                        FMA2(acc[q][1], iv, wA.y);
                        FMA2(acc[q][2], iv, wB.x);
                        FMA2(acc[q][3], iv, wB.y);
                        FMA2(acc[q][4], iv, wC.x);
                        FMA2(acc[q][5], iv, wC.y);
                        FMA2(acc[q][6], iv, wD.x);
                        FMA2(acc[q][7], iv, wD.y);
                    }
                }
            }
        }

        if (runA && cc + 4 < CIN) {
#pragma unroll
            for (int s = 0; s < 4; s++) BILIN(cur ^ 1, s, pf[s]);
        }
        __syncthreads();
    }
#undef BILIN
#undef LOAD6

    // ---- epilogue 1: BN + ReLU, stage vals in smem (overlay s_w, now dead)
    float4* s_vals = (float4*)&s_w[0][0][0];   // [64 ci][128 slots] float4 (128KB)
    const int slot = tid & 127;
#pragma unroll
    for (int j = 0; j < 8; j++) {
        float va[4], vb[4];
#pragma unroll
        for (int q = 0; q < 4; q++) upk2(acc[q][j], va[q], vb[q]);
        const int cr = 16 * cg + 2 * j;
        const float sa = s_scale[cr],     sha = s_shift[cr];
        const float sb = s_scale[cr + 1], shb = s_shift[cr + 1];
        float4 oa, ob;
        oa.x = fmaxf(fmaf(sa, va[0], sha), 0.f);
        oa.y = fmaxf(fmaf(sa, va[1], sha), 0.f);
        oa.z = fmaxf(fmaf(sa, va[2], sha), 0.f);
        oa.w = fmaxf(fmaf(sa, va[3], sha), 0.f);
        ob.x = fmaxf(fmaf(sb, vb[0], shb), 0.f);
        ob.y = fmaxf(fmaf(sb, vb[1], shb), 0.f);
        ob.z = fmaxf(fmaf(sb, vb[2], shb), 0.f);
        ob.w = fmaxf(fmaf(sb, vb[3], shb), 0.f);
        s_vals[cr * 128 + slot]       = oa;
        s_vals[(cr + 1) * 128 + slot] = ob;
    }
    __syncthreads();

    // ---- epilogue 2: COMPLETE conv1x1 (64 ch, ascending) + BN2 + threshold --
    const int c2b = 2 * cg;                // this thread covers co2 c2b, c2b+1
    unsigned long long p01[2], p23[2];
#pragma unroll
    for (int c = 0; c < 2; c++) { p01[c] = 0ull; p23[c] = 0ull; }
#pragma unroll
    for (int j = 0; j < 64; j++) {
        float4 v = s_vals[j * 128 + slot];
        unsigned long long i01 = pk2(v.x, v.y);
        unsigned long long i23 = pk2(v.z, v.w);
#pragma unroll
        for (int c = 0; c < 2; c++) {
            unsigned long long w = s_w2[c2b + c][j];
            FMA2(p01[c], i01, w);
            FMA2(p23[c], i23, w);
        }
    }

    const int oy = y0t + yg;
    const int ox = x0t + 4 * xg;
    const size_t rowoff = ((size_t)oy << 8) + ox;
#pragma unroll
    for (int c = 0; c < 2; c++) {
        const int co2 = c2b + c;
        float f0, f1, f2, f3;
        upk2(p01[c], f0, f1);
        upk2(p23[c], f2, f3);
        const float sc = s_scale2[co2], sh = s_shift2[co2];
        float o0 = fmaf(sc, f0, sh), o1 = fmaf(sc, f1, sh);
        float o2 = fmaf(sc, f2, sh), o3 = fmaf(sc, f3, sh);
        float4 xf;
        xf.x = (o0 > 1.0f) ? o0 : 0.f;
        xf.y = (o1 > 1.0f) ? o1 : 0.f;
        xf.z = (o2 > 1.0f) ? o2 : 0.f;
        xf.w = (o3 > 1.0f) ? o3 : 0.f;
        *(float4*)(g_xf + (((size_t)b * COUT + co2) << 16) + rowoff) = xf;
    }
}

// ---------------- fused rowsum + ws + rowmax + NMS + per-segment top-8 ------
// block = (plane, 16-row segment). rs computed per-column in registers.
__global__ __launch_bounds__(256) void k_nms() {
    __shared__ __align__(16) float s_xf[24][264];   // data cols 2..257; halo 0
    __shared__ __align__(16) float s_ws[20][264];   // data cols 2..257; halo -1
    float (*s_rm)[256] = (float (*)[256])&s_xf[0][0];           // overlay
    unsigned long long* s_keys = (unsigned long long*)&s_ws[0][0]; // overlay

    const int bid = blockIdx.x;
    const int pl = bid >> 4;
    const int seg = bid & 15;
    const int y0 = seg * 16;
    const int x = threadIdx.x;
    const float* xf = g_xf + ((size_t)pl << 16);

    // stage xf rows y0-4 .. y0+19 at col index x+2; zero halo & OOB rows
#pragma unroll
    for (int i = 0; i < 24; i++) {
        int row = y0 - 4 + i;
        s_xf[i][x + 2] = (row >= 0 && row < 256) ? xf[(row << 8) + x] : 0.f;
    }
    if (x < 96) {
        int rr = x >> 2, which = x & 3;
        const int idxs[4] = {0, 1, 258, 259};
        s_xf[rr][idxs[which]] = 0.f;
        if (rr + 12 < 24) {} // (24 rows: handled below)
    }
    if (x >= 96 && x < 192) {
        int i2 = x - 96;
        int rr = 12 + (i2 >> 2), which = i2 & 3;
        const int idxs[4] = {0, 1, 258, 259};
        s_xf[rr][idxs[which]] = 0.f;
    }
    if (x < 80) {
        int rr = x >> 2, which = x & 3;
        const int idxs[4] = {0, 1, 258, 259};
        s_ws[rr][idxs[which]] = -1.f;
    }
    __syncthreads();

    // rs per column in registers (rows y0-4 .. y0+19)
    float rsv[24];
#pragma unroll
    for (int i = 0; i < 24; i++) {
        const float* f = &s_xf[i][x];
        rsv[i] = f[0] + f[1] + f[2] + f[3] + f[4];
    }

    // ws rows y0-2 .. y0+17 (OOB rows = -1)
#pragma unroll
    for (int i = 0; i < 20; i++) {
        int y = y0 - 2 + i;
        float w;
        if (y >= 0 && y < 256)
            w = rsv[i] + rsv[i + 1] + rsv[i + 2] + rsv[i + 3] + rsv[i + 4];
        else
            w = -1.f;
        s_ws[i][x + 2] = w;
    }
    __syncthreads();   // s_xf reads done -> s_rm may overwrite

#pragma unroll
    for (int i = 0; i < 20; i++) {
        const float* wr = &s_ws[i][x];
        s_rm[i][x] = fmaxf(fmaxf(fmaxf(wr[0], wr[1]), fmaxf(wr[2], wr[3])), wr[4]);
    }
    __syncthreads();

    unsigned long long k[8];
#pragma unroll
    for (int j = 0; j < 8; j++) k[j] = 0ull;

#pragma unroll
    for (int i = 0; i < 16; i++) {
        float m = fmaxf(fmaxf(fmaxf(s_rm[i][x], s_rm[i + 1][x]),
                              fmaxf(s_rm[i + 2][x], s_rm[i + 3][x])),
                        s_rm[i + 4][x]);
        float v = s_ws[i + 2][x + 2];
        if (v == m) {
            unsigned pos = (unsigned)(((y0 + i) << 8) + x);
            unsigned long long key =
                ((unsigned long long)__float_as_uint(v) << 32) | (unsigned)(~pos);
            if (key > k[7]) {
                int p = 7;
#pragma unroll
                for (int q = 7; q > 0; q--) {
                    if (key > k[q - 1]) { k[q] = k[q - 1]; p = q - 1; }
                }
                k[p] = key;
            }
        }
    }
    __syncthreads();   // s_ws reads done -> s_keys may overwrite

#pragma unroll
    for (int j = 0; j < 8; j++) s_keys[x * 8 + j] = k[j];
    __syncthreads();

    for (int off = 128; off > 0; off >>= 1) {
        if (x < off) {
            unsigned long long* a = &s_keys[x * 8];
            unsigned long long* b = &s_keys[(x + off) * 8];
            unsigned long long out[8];
            int i = 0, j = 0;
#pragma unroll
            for (int t = 0; t < 8; t++)
                out[t] = (a[i] >= b[j]) ? a[i++] : b[j++];
#pragma unroll
            for (int t = 0; t < 8; t++) a[t] = out[t];
        }
        __syncthreads();
    }
    if (x < 8) g_seg[bid * 8 + x] = s_keys[x];
}

// ---------------- top-k stage 2: parallel merge + spread gather -------------
__global__ __launch_bounds__(224) void k_topk2(float* __restrict__ out) {
    __shared__ unsigned long long s[NSEG * 8];
    const int bc = blockIdx.x;
    const int tid = threadIdx.x;

    if (tid < NSEG * 8) s[tid] = g_seg[bc * (NSEG * 8) + tid];
    __syncthreads();

    for (int off = NSEG / 2; off > 0; off >>= 1) {
        if (tid < off) {
            unsigned long long* a = &s[tid * 8];
            unsigned long long* b = &s[(tid + off) * 8];
            unsigned long long m[8];
            int i = 0, j = 0;
#pragma unroll
            for (int t = 0; t < 8; t++)
                m[t] = (a[i] >= b[j]) ? a[i++] : b[j++];
#pragma unroll
            for (int t = 0; t < 8; t++) a[t] = m[t];
        }
        __syncthreads();
    }

    if (tid < 200) {
        const int slotk = tid / 25;
        const int e = tid - slotk * 25;
        unsigned pos = ~(unsigned)(s[slotk] & 0xFFFFFFFFull);
        int h = pos >> 8, w = pos & 255;
        int yy = h + e / 5 - 2;
        int xx = w + e % 5 - 2;
        float v = 0.f;
        if (yy >= 0 && yy < 256 && xx >= 0 && xx < 256)
            v = g_xf[((size_t)bc << 16) + (yy << 8) + xx];
        out[(bc * 8 + slotk) * 25 + e] = v;
    }
    if (tid < 32) {
        const int slotk = tid >> 2;
        const int c = tid & 3;
        unsigned pos = ~(unsigned)(s[slotk] & 0xFFFFFFFFull);
        int h = pos >> 8, w = pos & 255;
        int val;
        if (c == 0)      val = min(max(w - 2, 0), 255);
        else if (c == 1) val = min(max(h - 2, 0), 255);
        else if (c == 2) val = min(max(w + 2, 0), 255);
        else             val = min(max(h + 2, 0), 255);
        out[B_ * COUT * NUM_ * 25 + (bc * 8 + slotk) * 4 + c] = (float)val;
    }
}

// ---------------- launch ------------------------------------------------------
extern "C" void kernel_launch(void* const* d_in, const int* in_sizes, int n_in,
                              void* d_out, int out_size) {
    const float* x      = (const float*)d_in[0];
    const float* w1     = (const float*)d_in[1];
    const float* b1     = (const float*)d_in[2];
    const float* gamma1 = (const float*)d_in[3];
    const float* beta1  = (const float*)d_in[4];
    const float* mean1  = (const float*)d_in[5];
    const float* var1   = (const float*)d_in[6];
    const float* w2     = (const float*)d_in[7];
    const float* gamma2 = (const float*)d_in[8];
    const float* beta2  = (const float*)d_in[9];
    const float* mean2  = (const float*)d_in[10];
    const float* var2   = (const float*)d_in[11];
    float* out = (float*)d_out;

    cudaFuncSetAttribute(k_conv1, cudaFuncAttributeMaxDynamicSharedMemorySize,
                         C1_SMEM_TOTAL);

    dim3 cg(2, 64, B_);
    k_conv1<<<cg, 512, C1_SMEM_TOTAL>>>(x, w1, b1, gamma1, beta1, mean1, var1,
                                        w2, gamma2, beta2, mean2, var2);

    k_nms<<<B_ * COUT * NSEG, 256>>>();
    k_topk2<<<B_ * COUT, 224>>>(out);
}

// round 17
// speedup vs baseline: 1.1556x; 1.1556x over previous
#include <cuda_runtime.h>
#include <cstdint>

#define B_   8
#define CIN  64
#define COUT 8
#define H1   128
#define W1   128
#define H2   256
#define W2   256
#define PLANE (H2*W2)   /* 65536 */
#define NUM_ 8
#define NSEG 16

// ---------------- scratch (device globals; no allocation allowed) ----------
__device__ float g_p  [(size_t)2*B_*COUT*PLANE]; // conv2 partials per half
__device__ float g_xf [(size_t)B_*COUT*PLANE];   // conv2+BN, thresholded
__device__ unsigned long long g_seg[B_*COUT*NSEG*8]; // per-segment top-8 keys

// ---------------- packed f32x2 helpers --------------------------------------
__device__ __forceinline__ unsigned long long pk2(float lo, float hi) {
    unsigned long long r;
    asm("mov.b64 %0, {%1, %2};" : "=l"(r) : "f"(lo), "f"(hi));
    return r;
}
__device__ __forceinline__ void upk2(unsigned long long v, float& lo, float& hi) {
    asm("mov.b64 {%0, %1}, %2;" : "=f"(lo), "=f"(hi) : "l"(v));
}
#define FMA2(d, a, b) asm("fma.rn.f32x2 %0, %1, %2, %0;" : "+l"(d) : "l"(a), "l"(b))

// dynamic smem layout for conv1 (round-15 configuration)
#define C1_W_BYTES    (CIN * 9 * 16 * 8)            /* 73728 */
#define C1_IN_BYTES   (2 * 4 * 6 * 136 * 4)         /* 26112 */
#define C1_W2_BYTES   (8 * 32 * 8)                  /* 2048  */
#define C1_SS_BYTES   (2 * 32 * 4)                  /* 256   */
#define C1_SMEM_TOTAL (C1_W_BYTES + C1_IN_BYTES + C1_W2_BYTES + C1_SS_BYTES)

// ============================================================================
// conv1: fused bilinear-2x-upsample + conv3x3(64->64) + bias + BN + ReLU
//        + per-half partial of conv1x1 (writes g_p) — round-15 verbatim.
// ============================================================================
__global__ __launch_bounds__(256, 2) void k_conv1(
    const float* __restrict__ x,
    const float* __restrict__ w1, const float* __restrict__ b1,
    const float* __restrict__ gamma1, const float* __restrict__ beta1,
    const float* __restrict__ mean1, const float* __restrict__ var1,
    const float* __restrict__ w2)
{
    extern __shared__ __align__(16) unsigned char dsm[];
    unsigned long long (*s_w)[9][16] =
        (unsigned long long (*)[9][16])(dsm);                    // [ci][tap][pair]
    float (*s_in)[4][6][136] =
        (float (*)[4][6][136])(dsm + C1_W_BYTES);                // [buf][sub][r][c]
    unsigned long long (*s_w2)[32] =
        (unsigned long long (*)[32])(dsm + C1_W_BYTES + C1_IN_BYTES);
    float* s_scale = (float*)(dsm + C1_W_BYTES + C1_IN_BYTES + C1_W2_BYTES);
    float* s_shift = s_scale + 32;

    const int tid = threadIdx.x;
    const int xg = tid & 31;
    const int yg = (tid >> 5) & 3;
    const int cg = tid >> 7;               // 0/1: which 16-co group of the 32
    const int bz  = blockIdx.z;
    const int b    = bz >> 1;
    const int half = bz & 1;
    const int co0 = half * 32;
    const int x0t = blockIdx.x * 128;
    const int y0t = blockIdx.y * 4;

    const float* xb = x + (size_t)b * CIN * (H1 * W1);

    for (int i = tid; i < CIN * 9 * 16; i += 256) {
        int cp = i & 15; int rest = i >> 4;
        int p = rest % 9; int ci = rest / 9;
        int coA = co0 + 2 * cp;
        float wa = w1[((size_t)coA       * CIN + ci) * 9 + p];
        float wb = w1[((size_t)(coA + 1) * CIN + ci) * 9 + p];
        s_w[ci][p][cp] = pk2(wa, wb);
    }
    if (tid < 32) {
        int co = co0 + tid;
        float a = gamma1[co] * rsqrtf(var1[co] + 1e-5f);
        s_scale[tid] = a;
        s_shift[tid] = fmaf(a, b1[co] - mean1[co], beta1[co]);
    }
    {   // s_w2: exactly 256 entries (8 co2 x 32 ci-of-half)
        int co2 = tid >> 5, j = tid & 31;
        float w = w2[co2 * 64 + co0 + j];
        s_w2[co2][j] = pk2(w, w);
    }

    const bool runA = tid < 198;
    const int ur  = tid / 33;
    const int c0r = (tid - ur * 33) * 4;
    const int gy  = y0t + ur - 1;
    const int gx0 = x0t + c0r - 1;
    const int sy  = (gy - 1) >> 1;
    const int ro0 = min(max(sy, 0), H1 - 1) * W1;
    const int ro1 = min(max(sy + 1, 0), H1 - 1) * W1;
    const float wyv = (gy & 1) ? 0.25f : 0.75f;
    const int S   = (gx0 - 1) >> 1;
    const int cS0 = min(max(S, 0), W1 - 1);
    const int cS1 = min(max(S + 1, 0), W1 - 1);
    const int cS2 = min(max(S + 2, 0), W1 - 1);
    const bool rowOK = (gy >= 0) && (gy < H2);
    bool mok[4];
#pragma unroll
    for (int j = 0; j < 4; j++) {
        int gx = gx0 + j;
        mok[j] = rowOK && (gx >= 0) && (gx < W2);
    }

#define BILIN(buf, sub, pa) do {                                              \
        float p0a = (pa)[0], p0b = (pa)[1], p0c = (pa)[2];                    \
        float p1a = (pa)[3], p1b = (pa)[4], p1c = (pa)[5];                    \
        float t0 = p0a + 0.25f * (p0b - p0a);                                 \
        float t1 = p0a + 0.75f * (p0b - p0a);                                 \
        float t2 = p0b + 0.25f * (p0c - p0b);                                 \
        float t3 = p0b + 0.75f * (p0c - p0b);                                 \
        float u0 = p1a + 0.25f * (p1b - p1a);                                 \
        float u1 = p1a + 0.75f * (p1b - p1a);                                 \
        float u2 = p1b + 0.25f * (p1c - p1b);                                 \
        float u3 = p1b + 0.75f * (p1c - p1b);                                 \
        float4 o;                                                             \
        o.x = mok[0] ? (t0 + wyv * (u0 - t0)) : 0.f;                          \
        o.y = mok[1] ? (t1 + wyv * (u1 - t1)) : 0.f;                          \
        o.z = mok[2] ? (t2 + wyv * (u2 - t2)) : 0.f;                          \
        o.w = mok[3] ? (t3 + wyv * (u3 - t3)) : 0.f;                          \
        *(float4*)&s_in[buf][sub][ur][c0r] = o;                               \
    } while (0)

#define LOAD6(ci, pa) do {                                                    \
        const float* xp_ = xb + ((size_t)(ci) << 14);                         \
        (pa)[0] = xp_[ro0 + cS0]; (pa)[1] = xp_[ro0 + cS1];                   \
        (pa)[2] = xp_[ro0 + cS2];                                             \
        (pa)[3] = xp_[ro1 + cS0]; (pa)[4] = xp_[ro1 + cS1];                   \
        (pa)[5] = xp_[ro1 + cS2];                                             \
    } while (0)

    if (runA) {
        float pf[4][6];
#pragma unroll
        for (int s = 0; s < 4; s++) LOAD6(s, pf[s]);
#pragma unroll
        for (int s = 0; s < 4; s++) BILIN(0, s, pf[s]);
    }
    __syncthreads();

    unsigned long long acc[4][8];
#pragma unroll
    for (int q = 0; q < 4; q++)
#pragma unroll
        for (int j = 0; j < 8; j++) acc[q][j] = 0ull;

    for (int cc = 0; cc < CIN; cc += 4) {
        const int cur = (cc >> 2) & 1;

        float pf[4][6];
        if (runA && cc + 4 < CIN) {
#pragma unroll
            for (int s = 0; s < 4; s++) LOAD6(cc + 4 + s, pf[s]);
        }

#pragma unroll
        for (int sub = 0; sub < 4; sub++) {
            const int ci = cc + sub;
#pragma unroll
            for (int kr = 0; kr < 3; kr++) {
                const float* row = &s_in[cur][sub][yg + kr][4 * xg];
                float4 F = *(const float4*)row;
                float2 G = *(const float2*)(row + 4);
                unsigned long long Q[6];
                Q[0] = pk2(F.x, F.x);
                Q[1] = pk2(F.y, F.y);
                Q[2] = pk2(F.z, F.z);
                Q[3] = pk2(F.w, F.w);
                Q[4] = pk2(G.x, G.x);
                Q[5] = pk2(G.y, G.y);
#pragma unroll
                for (int kc = 0; kc < 3; kc++) {
                    const ulonglong2* wrow =
                        (const ulonglong2*)&s_w[ci][kr * 3 + kc][cg * 8];
                    ulonglong2 wA = wrow[0];
                    ulonglong2 wB = wrow[1];
                    ulonglong2 wC = wrow[2];
                    ulonglong2 wD = wrow[3];
#pragma unroll
                    for (int q = 0; q < 4; q++) {
                        unsigned long long iv = Q[kc + q];
                        FMA2(acc[q][0], iv, wA.x);
                        FMA2(acc[q][1], iv, wA.y);
                        FMA2(acc[q][2], iv, wB.x);
                        FMA2(acc[q][3], iv, wB.y);
                        FMA2(acc[q][4], iv, wC.x);
                        FMA2(acc[q][5], iv, wC.y);
                        FMA2(acc[q][6], iv, wD.x);
                        FMA2(acc[q][7], iv, wD.y);
                    }
                }
            }
        }

        if (runA && cc + 4 < CIN) {
#pragma unroll
            for (int s = 0; s < 4; s++) BILIN(cur ^ 1, s, pf[s]);
        }
        __syncthreads();
    }
#undef BILIN
#undef LOAD6

    // ---- epilogue 1: BN + ReLU, stage vals in smem (overlay s_w, now dead)
    float4* s_vals = (float4*)&s_w[0][0][0];   // [32 ci][128 slots] float4 (64KB)
    const int slot = tid & 127;
#pragma unroll
    for (int j = 0; j < 8; j++) {
        float va[4], vb[4];
#pragma unroll
        for (int q = 0; q < 4; q++) upk2(acc[q][j], va[q], vb[q]);
        const int cr = 16 * cg + 2 * j;
        const float sa = s_scale[cr],     sha = s_shift[cr];
        const float sb = s_scale[cr + 1], shb = s_shift[cr + 1];
        float4 oa, ob;
        oa.x = fmaxf(fmaf(sa, va[0], sha), 0.f);
        oa.y = fmaxf(fmaf(sa, va[1], sha), 0.f);
        oa.z = fmaxf(fmaf(sa, va[2], sha), 0.f);
        oa.w = fmaxf(fmaf(sa, va[3], sha), 0.f);
        ob.x = fmaxf(fmaf(sb, vb[0], shb), 0.f);
        ob.y = fmaxf(fmaf(sb, vb[1], shb), 0.f);
        ob.z = fmaxf(fmaf(sb, vb[2], shb), 0.f);
        ob.w = fmaxf(fmaf(sb, vb[3], shb), 0.f);
        s_vals[cr * 128 + slot]       = oa;
        s_vals[(cr + 1) * 128 + slot] = ob;
    }
    __syncthreads();

    // ---- epilogue 2: partial conv1x1 over this half's 32 channels ----------
    const int c2b = 4 * cg;
    unsigned long long p01[4], p23[4];
#pragma unroll
    for (int c = 0; c < 4; c++) { p01[c] = 0ull; p23[c] = 0ull; }
#pragma unroll
    for (int j = 0; j < 32; j++) {
        float4 v = s_vals[j * 128 + slot];
        unsigned long long i01 = pk2(v.x, v.y);
        unsigned long long i23 = pk2(v.z, v.w);
#pragma unroll
        for (int c = 0; c < 4; c++) {
            unsigned long long w = s_w2[c2b + c][j];
            FMA2(p01[c], i01, w);
            FMA2(p23[c], i23, w);
        }
    }

    const int oy = y0t + yg;
    const int ox = x0t + 4 * xg;
    float* pp = g_p + (((size_t)(half * B_ + b) * 8 + c2b) << 16) + (oy << 8) + ox;
#pragma unroll
    for (int c = 0; c < 4; c++) {
        float f0, f1, f2, f3;
        upk2(p01[c], f0, f1);
        upk2(p23[c], f2, f3);
        *(float4*)(pp + ((size_t)c << 16)) = make_float4(f0, f1, f2, f3);
    }
}

// ---------------- sum 2 half-partials + BN2 + threshold (xf only) -----------
__global__ __launch_bounds__(256) void k_sum2(
    const float* __restrict__ gamma2, const float* __restrict__ beta2,
    const float* __restrict__ mean2, const float* __restrict__ var2)
{
    __shared__ float s_scale[8], s_shift[8];
    const int tid = threadIdx.x;
    const int b  = blockIdx.x >> 6;
    const int y0 = (blockIdx.x & 63) * 4;
    const int r = tid >> 6;
    const int col0 = (tid & 63) * 4;

    if (tid < 8) {
        float a = gamma2[tid] * rsqrtf(var2[tid] + 1e-5f);
        s_scale[tid] = a;
        s_shift[tid] = beta2[tid] - a * mean2[tid];
    }
    __syncthreads();

    const size_t rowoff = ((size_t)(y0 + r) << 8) + col0;
#pragma unroll
    for (int co = 0; co < 8; co++) {
        float4 p0 = *(const float4*)(g_p + (((size_t)(0 * B_ + b) * 8 + co) << 16) + rowoff);
        float4 p1 = *(const float4*)(g_p + (((size_t)(1 * B_ + b) * 8 + co) << 16) + rowoff);
        float sx = p0.x + p1.x;
        float sy = p0.y + p1.y;
        float sz = p0.z + p1.z;
        float sw = p0.w + p1.w;
        const float sc = s_scale[co], sh = s_shift[co];
        float o0 = fmaf(sc, sx, sh), o1 = fmaf(sc, sy, sh);
        float o2 = fmaf(sc, sz, sh), o3 = fmaf(sc, sw, sh);
        float4 xf;
        xf.x = (o0 > 1.0f) ? o0 : 0.f;
        xf.y = (o1 > 1.0f) ? o1 : 0.f;
        xf.z = (o2 > 1.0f) ? o2 : 0.f;
        xf.w = (o3 > 1.0f) ? o3 : 0.f;
        *(float4*)(g_xf + (((size_t)b * COUT + co) << 16) + rowoff) = xf;
    }
}

// ---------------- fused rowsum + ws + rowmax + NMS + per-segment top-8 ------
// block = (plane, 16-row segment). rs computed per-column in registers.
// (round-16 version — correctness-validated)
__global__ __launch_bounds__(256) void k_nms() {
    __shared__ __align__(16) float s_xf[24][264];   // data cols 2..257; halo 0
    __shared__ __align__(16) float s_ws[20][264];   // data cols 2..257; halo -1
    float (*s_rm)[256] = (float (*)[256])&s_xf[0][0];           // overlay
    unsigned long long* s_keys = (unsigned long long*)&s_ws[0][0]; // overlay

    const int bid = blockIdx.x;
    const int pl = bid >> 4;
    const int seg = bid & 15;
    const int y0 = seg * 16;
    const int x = threadIdx.x;
    const float* xf = g_xf + ((size_t)pl << 16);

#pragma unroll
    for (int i = 0; i < 24; i++) {
        int row = y0 - 4 + i;
        s_xf[i][x + 2] = (row >= 0 && row < 256) ? xf[(row << 8) + x] : 0.f;
    }
    if (x < 96) {
        int rr = x >> 2, which = x & 3;
        const int idxs[4] = {0, 1, 258, 259};
        s_xf[rr][idxs[which]] = 0.f;
    }
    if (x >= 96 && x < 192) {
        int i2 = x - 96;
        int rr = 12 + (i2 >> 2), which = i2 & 3;
        const int idxs[4] = {0, 1, 258, 259};
        s_xf[rr][idxs[which]] = 0.f;
    }
    if (x < 80) {
        int rr = x >> 2, which = x & 3;
        const int idxs[4] = {0, 1, 258, 259};
        s_ws[rr][idxs[which]] = -1.f;
    }
    __syncthreads();

    float rsv[24];
#pragma unroll
    for (int i = 0; i < 24; i++) {
        const float* f = &s_xf[i][x];
        rsv[i] = f[0] + f[1] + f[2] + f[3] + f[4];
    }

#pragma unroll
    for (int i = 0; i < 20; i++) {
        int y = y0 - 2 + i;
        float w;
        if (y >= 0 && y < 256)
            w = rsv[i] + rsv[i + 1] + rsv[i + 2] + rsv[i + 3] + rsv[i + 4];
        else
            w = -1.f;
        s_ws[i][x + 2] = w;
    }
    __syncthreads();   // s_xf reads done -> s_rm may overwrite

#pragma unroll
    for (int i = 0; i < 20; i++) {
        const float* wr = &s_ws[i][x];
        s_rm[i][x] = fmaxf(fmaxf(fmaxf(wr[0], wr[1]), fmaxf(wr[2], wr[3])), wr[4]);
    }
    __syncthreads();

    unsigned long long k[8];
#pragma unroll
    for (int j = 0; j < 8; j++) k[j] = 0ull;

#pragma unroll
    for (int i = 0; i < 16; i++) {
        float m = fmaxf(fmaxf(fmaxf(s_rm[i][x], s_rm[i + 1][x]),
                              fmaxf(s_rm[i + 2][x], s_rm[i + 3][x])),
                        s_rm[i + 4][x]);
        float v = s_ws[i + 2][x + 2];
        if (v == m) {
            unsigned pos = (unsigned)(((y0 + i) << 8) + x);
            unsigned long long key =
                ((unsigned long long)__float_as_uint(v) << 32) | (unsigned)(~pos);
            if (key > k[7]) {
                int p = 7;
#pragma unroll
                for (int q = 7; q > 0; q--) {
                    if (key > k[q - 1]) { k[q] = k[q - 1]; p = q - 1; }
                }
                k[p] = key;
            }
        }
    }
    __syncthreads();   // s_ws reads done -> s_keys may overwrite

#pragma unroll
    for (int j = 0; j < 8; j++) s_keys[x * 8 + j] = k[j];
    __syncthreads();

    for (int off = 128; off > 0; off >>= 1) {
        if (x < off) {
            unsigned long long* a = &s_keys[x * 8];
            unsigned long long* b = &s_keys[(x + off) * 8];
            unsigned long long out[8];
            int i = 0, j = 0;
#pragma unroll
            for (int t = 0; t < 8; t++)
                out[t] = (a[i] >= b[j]) ? a[i++] : b[j++];
#pragma unroll
            for (int t = 0; t < 8; t++) a[t] = out[t];
        }
        __syncthreads();
    }
    if (x < 8) g_seg[bid * 8 + x] = s_keys[x];
}

// ---------------- top-k stage 2: parallel merge + spread gather -------------
__global__ __launch_bounds__(224) void k_topk2(float* __restrict__ out) {
    __shared__ unsigned long long s[NSEG * 8];
    const int bc = blockIdx.x;
    const int tid = threadIdx.x;

    if (tid < NSEG * 8) s[tid] = g_seg[bc * (NSEG * 8) + tid];
    __syncthreads();

    for (int off = NSEG / 2; off > 0; off >>= 1) {
        if (tid < off) {
            unsigned long long* a = &s[tid * 8];
            unsigned long long* b = &s[(tid + off) * 8];
            unsigned long long m[8];
            int i = 0, j = 0;
#pragma unroll
            for (int t = 0; t < 8; t++)
                m[t] = (a[i] >= b[j]) ? a[i++] : b[j++];
#pragma unroll
            for (int t = 0; t < 8; t++) a[t] = m[t];
        }
        __syncthreads();
    }

    if (tid < 200) {
        const int slotk = tid / 25;
        const int e = tid - slotk * 25;
        unsigned pos = ~(unsigned)(s[slotk] & 0xFFFFFFFFull);
        int h = pos >> 8, w = pos & 255;
        int yy = h + e / 5 - 2;
        int xx = w + e % 5 - 2;
        float v = 0.f;
        if (yy >= 0 && yy < 256 && xx >= 0 && xx < 256)
            v = g_xf[((size_t)bc << 16) + (yy << 8) + xx];
        out[(bc * 8 + slotk) * 25 + e] = v;
    }
    if (tid < 32) {
        const int slotk = tid >> 2;
        const int c = tid & 3;
        unsigned pos = ~(unsigned)(s[slotk] & 0xFFFFFFFFull);
        int h = pos >> 8, w = pos & 255;
        int val;
        if (c == 0)      val = min(max(w - 2, 0), 255);
        else if (c == 1) val = min(max(h - 2, 0), 255);
        else if (c == 2) val = min(max(w + 2, 0), 255);
        else             val = min(max(h + 2, 0), 255);
        out[B_ * COUT * NUM_ * 25 + (bc * 8 + slotk) * 4 + c] = (float)val;
    }
}

// ---------------- launch ------------------------------------------------------
extern "C" void kernel_launch(void* const* d_in, const int* in_sizes, int n_in,
                              void* d_out, int out_size) {
    const float* x      = (const float*)d_in[0];
    const float* w1     = (const float*)d_in[1];
    const float* b1     = (const float*)d_in[2];
    const float* gamma1 = (const float*)d_in[3];
    const float* beta1  = (const float*)d_in[4];
    const float* mean1  = (const float*)d_in[5];
    const float* var1   = (const float*)d_in[6];
    const float* w2     = (const float*)d_in[7];
    const float* gamma2 = (const float*)d_in[8];
    const float* beta2  = (const float*)d_in[9];
    const float* mean2  = (const float*)d_in[10];
    const float* var2   = (const float*)d_in[11];
    float* out = (float*)d_out;

    cudaFuncSetAttribute(k_conv1, cudaFuncAttributeMaxDynamicSharedMemorySize,
                         C1_SMEM_TOTAL);

    dim3 cg(2, 64, B_ * 2);
    k_conv1<<<cg, 256, C1_SMEM_TOTAL>>>(x, w1, b1, gamma1, beta1, mean1, var1, w2);

    k_sum2<<<B_ * 64, 256>>>(gamma2, beta2, mean2, var2);

    k_nms<<<B_ * COUT * NSEG, 256>>>();
    k_topk2<<<B_ * COUT, 224>>>(out);
}